// round 13
// baseline (speedup 1.0000x reference)
#include <cuda_runtime.h>
#include <stdint.h>
#include <math.h>

#define NTOK 16384
#define HD   4096
#define NE   64
#define NP   6
#define TK   8

#define NWARP    32
#define NTHREADS 1024
#define SLICE    128                 // columns per warp (32*128 = 4096)
#define UNIT_TOK 8
#define NUNITS   (NTOK / UNIT_TOK)   // 2048
#define GRID     148
#define PART_ROWS ((UNIT_TOK + 1) * 3)   // 27 (rows 24..26 = mean projection)

__device__ unsigned g_unit_ctr;

#define FMA2(acc, a, b) \
    asm("fma.rn.f32x2 %0, %1, %2, %0;" : "+l"(acc) : "l"(a), "l"(b))
#define ADD2(d, a, b) \
    asm("add.rn.f32x2 %0, %1, %2;" : "=l"(d) : "l"(a), "l"(b))

__global__ void reset_ctr_kernel() { g_unit_ctr = 0u; }

__global__ void __launch_bounds__(NTHREADS, 1)
kdtree_router_kernel(const float* __restrict__ x,
                     const float* __restrict__ mean,
                     const float* __restrict__ comp,
                     const float* __restrict__ cent,
                     float* __restrict__ out)
{
    __shared__ unsigned long long partU[PART_ROWS * 128];
    __shared__ float cent_s[NE * NP];
    __shared__ float centn_s[NE];
    __shared__ unsigned un_slot;

    const int tid  = threadIdx.x;
    const int lane = tid & 31;
    const int warp = tid >> 5;

    // ---------- prologue ----------
    if (tid < NE * NP) cent_s[tid] = cent[tid];
    __syncthreads();
    if (tid < NE) {
        float s = 0.f;
        #pragma unroll
        for (int p = 0; p < NP; p++) { float c = cent_s[tid*NP + p]; s += c * c; }
        centn_s[tid] = s;
    }

    // comp slice -> registers: 6 x ull2 (lane holds 4 consecutive floats)
    ulonglong2 cA[NP];
    #pragma unroll
    for (int p = 0; p < NP; p++)
        cA[p] = __ldg((const ulonglong2*)(comp + (size_t)p * HD + warp * SLICE) + lane);

    // mean projection partial -> part rows 24..26
    {
        ulonglong2 ma = __ldg((const ulonglong2*)(mean + warp * SLICE) + lane);
        unsigned long long acc[NP];
        #pragma unroll
        for (int p = 0; p < NP; p++) {
            acc[p] = 0ull;
            FMA2(acc[p], ma.x, cA[p].x);
            FMA2(acc[p], ma.y, cA[p].y);
        }
        unsigned long long u[3];
        #pragma unroll
        for (int j = 0; j < 3; j++) {
            float f0 = __uint_as_float((unsigned)(acc[2*j]   & 0xffffffffull)) +
                       __uint_as_float((unsigned)(acc[2*j]   >> 32));
            float f1 = __uint_as_float((unsigned)(acc[2*j+1] & 0xffffffffull)) +
                       __uint_as_float((unsigned)(acc[2*j+1] >> 32));
            u[j] = ((unsigned long long)__float_as_uint(f1) << 32) | __float_as_uint(f0);
        }
        #pragma unroll
        for (int o = 16; o >= 4; o >>= 1)
            #pragma unroll
            for (int j = 0; j < 3; j++) {
                unsigned long long v = __shfl_xor_sync(0xffffffffu, u[j], o);
                ADD2(u[j], u[j], v);
            }
        if (lane < 4)
            #pragma unroll
            for (int j = 0; j < 3; j++)
                partU[(UNIT_TOK*3 + j)*128 + warp*4 + lane] = u[j];
    }
    if (tid == 992) un_slot = atomicAdd(&g_unit_ctr, 1u);
    __syncthreads();

    // mean projection -> registers (all warps)
    float mpj[NP];
    #pragma unroll
    for (int j = 0; j < 3; j++) {
        unsigned long long u  = partU[(UNIT_TOK*3 + j)*128 + lane];
        unsigned long long v;
        v = partU[(UNIT_TOK*3 + j)*128 + lane + 32]; ADD2(u, u, v);
        v = partU[(UNIT_TOK*3 + j)*128 + lane + 64]; ADD2(u, u, v);
        v = partU[(UNIT_TOK*3 + j)*128 + lane + 96]; ADD2(u, u, v);
        #pragma unroll
        for (int o = 16; o >= 1; o >>= 1) {
            v = __shfl_xor_sync(0xffffffffu, u, o);
            ADD2(u, u, v);
        }
        mpj[2*j]   = __uint_as_float((unsigned)(u & 0xffffffffull));
        mpj[2*j+1] = __uint_as_float((unsigned)(u >> 32));
    }

    float* out_idx = out;
    float* out_tp  = out + (size_t)NTOK * TK;
    float* out_pr  = out + 2 * (size_t)NTOK * TK;

    unsigned un = un_slot;
    const char* xbase = (const char*)x;

    // first unit: preload tokens 0..1 (loop body expects buf[0..1] ready)
    ulonglong2 buf[4];
    {
        const char* tb = xbase + ((size_t)un * UNIT_TOK * HD + (size_t)warp * SLICE) * 4;
        buf[0] = __ldcs((const ulonglong2*)(tb              ) + lane);
        buf[1] = __ldcs((const ulonglong2*)(tb + (size_t)HD*4) + lane);
    }

    for (;;) {
        const char* tb = xbase + ((size_t)un * UNIT_TOK * HD + (size_t)warp * SLICE) * 4;
        buf[2] = __ldcs((const ulonglong2*)(tb + (size_t)2*HD*4) + lane);
        buf[3] = __ldcs((const ulonglong2*)(tb + (size_t)3*HD*4) + lane);

        unsigned nx;
        if (tid == 992) nx = atomicAdd(&g_unit_ctr, 1u);

        #pragma unroll
        for (int t = 0; t < UNIT_TOK; t++) {
            ulonglong2 xa = buf[t & 3];
            if (t + 4 < UNIT_TOK)
                buf[t & 3] = __ldcs((const ulonglong2*)(tb + (size_t)(t+4)*HD*4) + lane);

            unsigned long long acc[NP];
            #pragma unroll
            for (int p = 0; p < NP; p++) {
                acc[p] = 0ull;
                FMA2(acc[p], xa.x, cA[p].x);
                FMA2(acc[p], xa.y, cA[p].y);
            }
            unsigned long long u[3];
            #pragma unroll
            for (int j = 0; j < 3; j++) {
                float f0 = __uint_as_float((unsigned)(acc[2*j]   & 0xffffffffull)) +
                           __uint_as_float((unsigned)(acc[2*j]   >> 32));
                float f1 = __uint_as_float((unsigned)(acc[2*j+1] & 0xffffffffull)) +
                           __uint_as_float((unsigned)(acc[2*j+1] >> 32));
                u[j] = ((unsigned long long)__float_as_uint(f1) << 32) | __float_as_uint(f0);
            }
            #pragma unroll
            for (int o = 16; o >= 4; o >>= 1)
                #pragma unroll
                for (int j = 0; j < 3; j++) {
                    unsigned long long v = __shfl_xor_sync(0xffffffffu, u[j], o);
                    ADD2(u[j], u[j], v);
                }
            if (lane < 4)
                #pragma unroll
                for (int j = 0; j < 3; j++)
                    partU[(t*3 + j)*128 + warp*4 + lane] = u[j];
        }

        if (tid == 992) un_slot = nx;
        __syncthreads();                 // partials + next unit id visible
        const unsigned un2 = un_slot;

        // prefetch next unit's first two tokens (overlaps epilogue)
        if (un2 < NUNITS) {
            const char* tb2 = xbase + ((size_t)un2 * UNIT_TOK * HD + (size_t)warp * SLICE) * 4;
            buf[0] = __ldcs((const ulonglong2*)(tb2               ) + lane);
            buf[1] = __ldcs((const ulonglong2*)(tb2 + (size_t)HD*4) + lane);
        }

        if (warp < UNIT_TOK) {
            // ---- epilogue: warp w finalizes token un*8 + w ----
            const unsigned tok = un * UNIT_TOK + warp;

            float pr[NP];
            #pragma unroll
            for (int j = 0; j < 3; j++) {
                unsigned long long u  = partU[(warp*3 + j)*128 + lane];
                unsigned long long v;
                v = partU[(warp*3 + j)*128 + lane + 32]; ADD2(u, u, v);
                v = partU[(warp*3 + j)*128 + lane + 64]; ADD2(u, u, v);
                v = partU[(warp*3 + j)*128 + lane + 96]; ADD2(u, u, v);
                #pragma unroll
                for (int o = 16; o >= 1; o >>= 1) {
                    v = __shfl_xor_sync(0xffffffffu, u, o);
                    ADD2(u, u, v);
                }
                pr[2*j]   = __uint_as_float((unsigned)(u & 0xffffffffull)) - mpj[2*j];
                pr[2*j+1] = __uint_as_float((unsigned)(u >> 32))           - mpj[2*j+1];
            }

            float pn = 0.f;
            #pragma unroll
            for (int p = 0; p < NP; p++) pn += pr[p] * pr[p];

            const int e0 = lane, e1 = lane + 32;
            float dot0 = 0.f, dot1 = 0.f;
            #pragma unroll
            for (int p = 0; p < NP; p++) {
                dot0 += pr[p] * cent_s[e0*NP + p];
                dot1 += pr[p] * cent_s[e1*NP + p];
            }
            float d20 = pn - 2.f*dot0 + centn_s[e0];
            float d21 = pn - 2.f*dot1 + centn_s[e1];
            float s0 = -sqrtf(fmaxf(d20, 0.f));
            float s1 = -sqrtf(fmaxf(d21, 0.f));

            float m = fmaxf(s0, s1);
            #pragma unroll
            for (int o = 16; o > 0; o >>= 1)
                m = fmaxf(m, __shfl_xor_sync(0xffffffffu, m, o));
            float ex0 = expf(s0 - m);
            float ex1 = expf(s1 - m);
            float sum = ex0 + ex1;
            #pragma unroll
            for (int o = 16; o > 0; o >>= 1)
                sum += __shfl_xor_sync(0xffffffffu, sum, o);
            float p0 = ex0 / sum;
            float p1 = ex1 / sum;

            out_pr[(size_t)tok*NE + e0] = p0;
            out_pr[(size_t)tok*NE + e1] = p1;

            // top-8 via 8-round warp argmax; tie-break = lower index (jax.lax.top_k)
            unsigned long long k0 = ((unsigned long long)__float_as_uint(p0) << 32) | (unsigned)(NE-1 - e0);
            unsigned long long k1 = ((unsigned long long)__float_as_uint(p1) << 32) | (unsigned)(NE-1 - e1);
            float tsum = 0.f, myp = 0.f;
            int myi = 0;
            #pragma unroll
            for (int r = 0; r < TK; r++) {
                unsigned long long b = (k0 > k1) ? k0 : k1;
                #pragma unroll
                for (int o = 16; o > 0; o >>= 1) {
                    unsigned long long v = __shfl_xor_sync(0xffffffffu, b, o);
                    if (v > b) b = v;
                }
                int idx = NE-1 - (int)(b & 0xffull);
                float pv = __uint_as_float((unsigned)(b >> 32));
                tsum += pv;
                if (lane == r) { myp = pv; myi = idx; }
                if (idx == e0) k0 = 0ull;
                if (idx == e1) k1 = 0ull;
            }
            if (lane < TK) {
                out_idx[(size_t)tok*TK + lane] = (float)myi;
                out_tp [(size_t)tok*TK + lane] = myp / tsum;
            }
        }
        __syncthreads();                 // part[] free for next unit's STS
        if (un2 >= NUNITS) break;
        un = un2;
    }
}

extern "C" void kernel_launch(void* const* d_in, const int* in_sizes, int n_in,
                              void* d_out, int out_size)
{
    const float* x    = (const float*)d_in[0];
    const float* mean = (const float*)d_in[1];
    const float* comp = (const float*)d_in[2];
    const float* cent = (const float*)d_in[3];
    float* out = (float*)d_out;

    reset_ctr_kernel<<<1, 1>>>();
    kdtree_router_kernel<<<GRID, NTHREADS>>>(x, mean, comp, cent, out);
}